// round 5
// baseline (speedup 1.0000x reference)
#include <cuda_runtime.h>
#include <cstdint>

// ---------------------------------------------------------------------------
// TensorTrain forward, right-to-left vector sweep, fp32x2 register-tiled GEMM.
//   v7[l,s]   = sum_p x[s,7,p] * core_last[l,p]
//   v_j[l,s]  = sum_{p,r} cores_mid[j][l,p,r] * x[s,j+1,p] * v_{j+1}[r,s]
//   out[s,c]  = sum_{p,r} core_first[c,p,r] * x[s,0,p] * v_0[r,s]
// Chain state lives in 7 sequential [l][s] buffers; mid steps accumulate
// split-K contributions directly into the next buffer via REDG atomics
// (no separate reduce kernel). W pre-rearranged once to [p][r][2l] dup'd.
// ---------------------------------------------------------------------------

namespace {

constexpr int Bn = 4096;
constexpr int Nn = 8;
constexpr int Fn = 64;
constexpr int Dn = 64;
constexpr int Cn = 10;
constexpr int NMID = 6;

constexpr int KS = 32;       // split-K over p (mid kernel)
constexpr int PC = Fn / KS;  // 2 p per CTA
constexpr int KSF = 8;       // split-K over p (final kernel)
constexpr int PCF = Fn / KSF;

constexpr int VS = 132;      // smem row stride (floats) for v_t / x_t

// dynamic smem layout (floats): v_t[64][VS] | w2[2][64][128] | x_t[2][VS]
constexpr int SM_VT = 0;
constexpr int SM_W2 = Dn * VS;
constexpr int SM_XT = SM_W2 + PC * Dn * 128;
constexpr int SM_MID_BYTES = (SM_XT + PC * VS) * 4;

// device scratch (no allocations allowed)
__device__ float g_vbuf[(NMID + 1) * Bn * Dn];            // 7 MB chain states
__device__ float g_partf[(size_t)KSF * Bn * 12];          // final partials
__device__ float g_w2[(size_t)NMID * Fn * Dn * 2 * Dn];   // 12.6 MB dup'd W

typedef unsigned long long ull;

__device__ __forceinline__ ull dup2(float a) {
  ull r; asm("mov.b64 %0, {%1, %1};" : "=l"(r) : "f"(a)); return r;
}
__device__ __forceinline__ void unpack2(ull v, float& a, float& b) {
  asm("mov.b64 {%0, %1}, %2;" : "=f"(a), "=f"(b) : "l"(v));
}
__device__ __forceinline__ ull ffma2(ull a, ull b, ull c) {
  ull d; asm("fma.rn.f32x2 %0, %1, %2, %3;" : "=l"(d) : "l"(a), "l"(b), "l"(c));
  return d;
}
__device__ __forceinline__ ull fmul2(ull a, ull b) {
  ull d; asm("mul.rn.f32x2 %0, %1, %2;" : "=l"(d) : "l"(a), "l"(b));
  return d;
}

// ---------------------------------------------------------------------------
// Pre-rearrange mid cores: g_w2[j][p][r][2l(+1)] = cmid[j][l][p][r], dup'd.
// ---------------------------------------------------------------------------
__global__ __launch_bounds__(256) void preconv_w_kernel(const float* __restrict__ cmid) {
  __shared__ float tmp[Dn * 68];  // [l][r], stride 68
  const int t = threadIdx.x;
  const int p = blockIdx.x & 63;
  const int j = blockIdx.x >> 6;

#pragma unroll
  for (int it = 0; it < (Dn * Dn) / 256; ++it) {
    int idx = it * 256 + t;
    int r = idx & 63;
    int l = idx >> 6;
    tmp[l * 68 + r] = cmid[(((size_t)j * Dn + l) * Fn + p) * Dn + r];
  }
  __syncthreads();

  float* out = g_w2 + ((size_t)j * Fn + p) * (Dn * 2 * Dn);
#pragma unroll
  for (int it = 0; it < (Dn * 2 * Dn) / 256; ++it) {
    int idx = it * 256 + t;
    int col = idx & 127;
    int r = idx >> 7;
    out[r * 128 + col] = tmp[(col >> 1) * 68 + r];
  }
}

// ---------------------------------------------------------------------------
// init: dst[l][s] = sum_p x[s,7,p] * core_last[l,p]
// ---------------------------------------------------------------------------
__global__ __launch_bounds__(256) void init_v_kernel(const float* __restrict__ x,
                                                     const float* __restrict__ clast,
                                                     float* __restrict__ dst) {
  __shared__ __align__(16) float cl[Fn * 68];  // [p][l]
  const int tid = threadIdx.x;
  const int sl = tid & 63;
  const int l0 = (tid >> 6) * 16;
  const int s = blockIdx.x * 64 + sl;

#pragma unroll
  for (int k = 0; k < (Dn * Fn) / 256; ++k) {
    int idx = k * 256 + tid;
    int p = idx & 63;
    int l = idx >> 6;
    cl[p * 68 + l] = clast[l * Fn + p];
  }
  float xv[Fn];
  {
    const float4* xp =
        reinterpret_cast<const float4*>(x + (size_t)s * (Nn * Fn) + 7 * Fn);
#pragma unroll
    for (int k = 0; k < Fn / 4; ++k) {
      float4 t = xp[k];
      xv[4 * k] = t.x; xv[4 * k + 1] = t.y; xv[4 * k + 2] = t.z; xv[4 * k + 3] = t.w;
    }
  }
  __syncthreads();

  ull acc[8];
#pragma unroll
  for (int q = 0; q < 8; ++q) acc[q] = 0ull;
#pragma unroll 8
  for (int p = 0; p < Fn; ++p) {
    ull t2 = dup2(xv[p]);
    const ulonglong2* rp = reinterpret_cast<const ulonglong2*>(&cl[p * 68 + l0]);
#pragma unroll
    for (int q = 0; q < 4; ++q) {
      ulonglong2 cc = rp[q];
      acc[2 * q]     = ffma2(cc.x, t2, acc[2 * q]);
      acc[2 * q + 1] = ffma2(cc.y, t2, acc[2 * q + 1]);
    }
  }
#pragma unroll
  for (int q = 0; q < 8; ++q) {
    float a, b;
    unpack2(acc[q], a, b);
    dst[(size_t)(l0 + 2 * q) * Bn + s] = a;
    dst[(size_t)(l0 + 2 * q + 1) * Bn + s] = b;
  }
}

// ---------------------------------------------------------------------------
// mid step: dst[l][s] += sum_{p in chunk} sum_r W[l,p,r]*x[s,t,p]*src[r,s]
// grid (Bn/128, KS), 128 threads. Thread tile: 8 samples (4 pairs) x 8 l.
// Split-K contributions merged via REDG atomics (dst pre-zeroed).
// ---------------------------------------------------------------------------
__global__ __launch_bounds__(128) void mid_step_kernel(const float* __restrict__ x,
                                                       const float* __restrict__ src,
                                                       float* __restrict__ dst,
                                                       int j, int tIdx) {
  extern __shared__ __align__(16) float sm[];
  float* v_t = sm + SM_VT;   // [r][s], stride VS
  float* w2  = sm + SM_W2;   // [p][r][2l], stride 128
  float* x_t = sm + SM_XT;   // [p][s], stride VS

  const int tid = threadIdx.x;
  const int si = tid & 15;
  const int li = tid >> 4;
  const int s0 = blockIdx.x * 128;
  const int pbase = blockIdx.y * PC;

  // stage w2 (64KB straight copy of two pre-rearranged 32KB tiles)
  {
    const float4* srcw = reinterpret_cast<const float4*>(
        g_w2 + ((size_t)j * Fn + pbase) * (Dn * 2 * Dn));
    float4* dstw = reinterpret_cast<float4*>(w2);
#pragma unroll
    for (int it = 0; it < (PC * Dn * 2 * Dn) / (4 * 128); ++it)
      dstw[it * 128 + tid] = srcw[it * 128 + tid];
  }
  // stage v_t: straight copy of src[r][s0..s0+127]
#pragma unroll
  for (int it = 0; it < 16; ++it) {
    int idx = it * 128 + tid;
    int c4 = idx & 31;
    int r = idx >> 5;
    float4 t = *reinterpret_cast<const float4*>(&src[(size_t)r * Bn + s0 + c4 * 4]);
    *reinterpret_cast<float4*>(&v_t[r * VS + c4 * 4]) = t;
  }
  // stage x_t[p][s]
  {
    float2 t = *reinterpret_cast<const float2*>(
        x + (size_t)(s0 + tid) * (Nn * Fn) + (size_t)tIdx * Fn + pbase);
    x_t[0 * VS + tid] = t.x;
    x_t[1 * VS + tid] = t.y;
  }
  __syncthreads();

  ull xp0[4], xp1[4];
#pragma unroll
  for (int q = 0; q < 4; ++q) {
    xp0[q] = *reinterpret_cast<const ull*>(&x_t[0 * VS + si * 8 + 2 * q]);
    xp1[q] = *reinterpret_cast<const ull*>(&x_t[1 * VS + si * 8 + 2 * q]);
  }

  ull acc[4][8];
#pragma unroll
  for (int jj = 0; jj < 4; ++jj)
#pragma unroll
    for (int q = 0; q < 8; ++q) acc[jj][q] = 0ull;

#pragma unroll 4
  for (int r = 0; r < Dn; ++r) {
    const float* vrow = &v_t[r * VS + si * 8];
    ulonglong2 va = *reinterpret_cast<const ulonglong2*>(vrow);
    ulonglong2 vb = *reinterpret_cast<const ulonglong2*>(vrow + 4);

    // p = 0
    {
      ull a0 = fmul2(va.x, xp0[0]);
      ull a1 = fmul2(va.y, xp0[1]);
      ull a2 = fmul2(vb.x, xp0[2]);
      ull a3 = fmul2(vb.y, xp0[3]);
      const ull* wrow =
          reinterpret_cast<const ull*>(&w2[(0 * Dn + r) * 128 + li * 16]);
#pragma unroll
      for (int q = 0; q < 8; ++q) {
        ull wq = wrow[q];
        acc[0][q] = ffma2(a0, wq, acc[0][q]);
        acc[1][q] = ffma2(a1, wq, acc[1][q]);
        acc[2][q] = ffma2(a2, wq, acc[2][q]);
        acc[3][q] = ffma2(a3, wq, acc[3][q]);
      }
    }
    // p = 1
    {
      ull a0 = fmul2(va.x, xp1[0]);
      ull a1 = fmul2(va.y, xp1[1]);
      ull a2 = fmul2(vb.x, xp1[2]);
      ull a3 = fmul2(vb.y, xp1[3]);
      const ull* wrow =
          reinterpret_cast<const ull*>(&w2[(1 * Dn + r) * 128 + li * 16]);
#pragma unroll
      for (int q = 0; q < 8; ++q) {
        ull wq = wrow[q];
        acc[0][q] = ffma2(a0, wq, acc[0][q]);
        acc[1][q] = ffma2(a1, wq, acc[1][q]);
        acc[2][q] = ffma2(a2, wq, acc[2][q]);
        acc[3][q] = ffma2(a3, wq, acc[3][q]);
      }
    }
  }

  // accumulate into dst (REDG; result unused -> ptxas emits RED)
#pragma unroll
  for (int q = 0; q < 8; ++q) {
    int l = li * 8 + q;
    float* base = &dst[(size_t)l * Bn + s0 + si * 8];
#pragma unroll
    for (int jj = 0; jj < 4; ++jj) {
      float a, b;
      unpack2(acc[jj][q], a, b);
      atomicAdd(base + 2 * jj, a);
      atomicAdd(base + 2 * jj + 1, b);
    }
  }
}

// ---------------------------------------------------------------------------
// final: partial_out[ks][s,c] = sum_{p in chunk} sum_r cfirst[c,p,r]*x[s,0,p]*v[r,s]
// ---------------------------------------------------------------------------
__global__ __launch_bounds__(128) void final_kernel(const float* __restrict__ x,
                                                    const float* __restrict__ cfirst,
                                                    const float* __restrict__ vsrc) {
  __shared__ __align__(16) float fs[Dn * 12];  // [r][c]
  const int tid = threadIdx.x;
  const int s = blockIdx.x * 128 + tid;
  const int pbase = blockIdx.y * PCF;

  float vr[Dn];
#pragma unroll
  for (int r = 0; r < Dn; ++r) vr[r] = vsrc[(size_t)r * Bn + s];

  float xr[PCF];
  {
    const float4* xp =
        reinterpret_cast<const float4*>(x + (size_t)s * (Nn * Fn) + pbase);
#pragma unroll
    for (int k = 0; k < PCF / 4; ++k) {
      float4 t = xp[k];
      xr[4 * k] = t.x; xr[4 * k + 1] = t.y; xr[4 * k + 2] = t.z; xr[4 * k + 3] = t.w;
    }
  }

  ull acc[5];
#pragma unroll
  for (int q = 0; q < 5; ++q) acc[q] = 0ull;

#pragma unroll 1
  for (int pp = 0; pp < PCF; ++pp) {
    __syncthreads();
    {
      const float* cp = cfirst + (size_t)(pbase + pp) * Dn;
#pragma unroll
      for (int k = 0; k < 5; ++k) {
        int idx = k * 128 + tid;
        int r = idx & 63;
        int c = idx >> 6;
        fs[r * 12 + c] = cp[(size_t)c * (Fn * Dn) + r];
      }
    }
    __syncthreads();
    const float xpv = xr[pp];
#pragma unroll 8
    for (int r = 0; r < Dn; ++r) {
      ull t2 = dup2(xpv * vr[r]);
      const float* base = &fs[r * 12];
      ulonglong2 a01 = *reinterpret_cast<const ulonglong2*>(base);
      ulonglong2 a23 = *reinterpret_cast<const ulonglong2*>(base + 4);
      ull a4 = *reinterpret_cast<const ull*>(base + 8);
      acc[0] = ffma2(a01.x, t2, acc[0]);
      acc[1] = ffma2(a01.y, t2, acc[1]);
      acc[2] = ffma2(a23.x, t2, acc[2]);
      acc[3] = ffma2(a23.y, t2, acc[3]);
      acc[4] = ffma2(a4, t2, acc[4]);
    }
  }

  float o[10];
#pragma unroll
  for (int q = 0; q < 5; ++q) unpack2(acc[q], o[2 * q], o[2 * q + 1]);
  float* op = g_partf + ((size_t)blockIdx.y * Bn + s) * 12;
  reinterpret_cast<float4*>(op)[0] = make_float4(o[0], o[1], o[2], o[3]);
  reinterpret_cast<float4*>(op)[1] = make_float4(o[4], o[5], o[6], o[7]);
  reinterpret_cast<float2*>(op + 8)[0] = make_float2(o[8], o[9]);
}

__global__ void reduce_out_kernel(float* __restrict__ out) {
  int i = blockIdx.x * blockDim.x + threadIdx.x;
  if (i < Bn * Cn) {
    int s = i / Cn;
    int c = i - s * Cn;
    float acc = 0.f;
#pragma unroll
    for (int k = 0; k < KSF; ++k) acc += g_partf[((size_t)k * Bn + s) * 12 + c];
    out[i] = acc;
  }
}

}  // namespace

extern "C" void kernel_launch(void* const* d_in, const int* in_sizes, int n_in,
                              void* d_out, int out_size) {
  const float* x = (const float*)d_in[0];       // (4096, 8, 64)
  const float* cfirst = (const float*)d_in[1];  // (10, 64, 64)
  const float* cmid = (const float*)d_in[2];    // (6, 64, 64, 64)
  const float* clast = (const float*)d_in[3];   // (64, 64)
  float* out = (float*)d_out;                   // (4096, 10)

  static bool setup_done = false;
  static float* vbuf = nullptr;
  if (!setup_done) {
    cudaFuncSetAttribute(mid_step_kernel,
                         cudaFuncAttributeMaxDynamicSharedMemorySize,
                         SM_MID_BYTES);
    cudaGetSymbolAddress((void**)&vbuf, g_vbuf);
    setup_done = true;
  }

  // zero accumulation targets (buffers 1..6) once per launch
  cudaMemsetAsync(vbuf + (size_t)Bn * Dn, 0,
                  (size_t)NMID * Bn * Dn * sizeof(float));

  preconv_w_kernel<<<NMID * Fn, 256>>>(cmid);
  init_v_kernel<<<Bn / 64, 256>>>(x, clast, vbuf);

  // executed step i (i=0..5) uses core j = 5-i, reads buf i, REDs into buf i+1
  for (int i = 0; i < NMID; ++i) {
    int j = NMID - 1 - i;
    mid_step_kernel<<<dim3(Bn / 128, KS), 128, SM_MID_BYTES>>>(
        x, vbuf + (size_t)i * Bn * Dn, vbuf + (size_t)(i + 1) * Bn * Dn,
        j, j + 1);
  }

  final_kernel<<<dim3(Bn / 128, KSF), 128>>>(x, cfirst,
                                             vbuf + (size_t)NMID * Bn * Dn);
  reduce_out_kernel<<<(Bn * Cn + 255) / 256, 256>>>(out);
}

// round 7
// speedup vs baseline: 1.1686x; 1.1686x over previous
#include <cuda_runtime.h>
#include <cstdint>

// ---------------------------------------------------------------------------
// TensorTrain forward, right-to-left vector sweep, fp32x2 register-tiled GEMM.
//   v7[l,s]   = sum_p x[s,7,p] * core_last[l,p]          (state stored [l][s])
//   v_j[l,s]  = sum_{p,r} cores_mid[j][l,p,r] * x[s,j+1,p] * v_{j+1}[r,s]
//   out[s,c]  = sum_{p,r} core_first[c,p,r] * x[s,0,p] * v_0[r,s]
// Mid cores pre-rearranged once to g_w2[j][p][r][2l] (value duplicated) so the
// FFMA2 b-operand streams straight from conflict-free LDS.128.
// Split-K = 16 over p; explicit partials + vectorized tree reduce.
// ---------------------------------------------------------------------------

namespace {

constexpr int Bn = 4096;
constexpr int Nn = 8;
constexpr int Fn = 64;
constexpr int Dn = 64;
constexpr int Cn = 10;
constexpr int NMID = 6;

constexpr int KS = 16;       // split-K over p (mid kernel)
constexpr int PC = Fn / KS;  // 4 p per CTA (2 staging phases of 2)
constexpr int KSF = 8;       // split-K over p (final kernel)
constexpr int PCF = Fn / KSF;

constexpr int VS = 132;      // smem row stride (floats) for v_t / x_t

// dynamic smem layout (floats): v_t[64][VS] | w2[2][64][128] | x_t[4][VS]
constexpr int SM_VT = 0;
constexpr int SM_W2 = Dn * VS;
constexpr int SM_XT = SM_W2 + 2 * Dn * 128;
constexpr int SM_MID_BYTES = (SM_XT + PC * VS) * 4;

// device scratch (no allocations allowed)
__device__ float g_v[Dn * Bn];                       // 1 MB chain state, [l][s]
__device__ float g_part[(size_t)KS * Bn * Dn];       // 16 MB split-K partials
__device__ float g_w2[(size_t)NMID * Fn * Dn * 2 * Dn];  // 12.6 MB dup'd W

typedef unsigned long long ull;

__device__ __forceinline__ ull dup2(float a) {
  ull r; asm("mov.b64 %0, {%1, %1};" : "=l"(r) : "f"(a)); return r;
}
__device__ __forceinline__ void unpack2(ull v, float& a, float& b) {
  asm("mov.b64 {%0, %1}, %2;" : "=f"(a), "=f"(b) : "l"(v));
}
__device__ __forceinline__ ull ffma2(ull a, ull b, ull c) {
  ull d; asm("fma.rn.f32x2 %0, %1, %2, %3;" : "=l"(d) : "l"(a), "l"(b), "l"(c));
  return d;
}
__device__ __forceinline__ ull fmul2(ull a, ull b) {
  ull d; asm("mul.rn.f32x2 %0, %1, %2;" : "=l"(d) : "l"(a), "l"(b));
  return d;
}

// ---------------------------------------------------------------------------
// Pre-rearrange mid cores: g_w2[j][p][r][2l(+1)] = cmid[j][l][p][r], dup'd.
// ---------------------------------------------------------------------------
__global__ __launch_bounds__(256) void preconv_w_kernel(const float* __restrict__ cmid) {
  __shared__ float tmp[Dn * 68];  // [l][r], stride 68
  const int t = threadIdx.x;
  const int p = blockIdx.x & 63;
  const int j = blockIdx.x >> 6;

#pragma unroll
  for (int it = 0; it < (Dn * Dn) / 256; ++it) {
    int idx = it * 256 + t;
    int r = idx & 63;
    int l = idx >> 6;
    tmp[l * 68 + r] = cmid[(((size_t)j * Dn + l) * Fn + p) * Dn + r];
  }
  __syncthreads();

  float* out = g_w2 + ((size_t)j * Fn + p) * (Dn * 2 * Dn);
#pragma unroll
  for (int it = 0; it < (Dn * 2 * Dn) / 256; ++it) {
    int idx = it * 256 + t;
    int col = idx & 127;   // 2l or 2l+1
    int r = idx >> 7;
    out[r * 128 + col] = tmp[(col >> 1) * 68 + r];
  }
}

// ---------------------------------------------------------------------------
// init: g_v[l][s] = sum_p x[s,7,p] * core_last[l,p]
// ---------------------------------------------------------------------------
__global__ __launch_bounds__(256) void init_v_kernel(const float* __restrict__ x,
                                                     const float* __restrict__ clast) {
  __shared__ __align__(16) float cl[Fn * 68];  // [p][l]
  const int tid = threadIdx.x;
  const int sl = tid & 63;
  const int l0 = (tid >> 6) * 16;
  const int s = blockIdx.x * 64 + sl;

#pragma unroll
  for (int k = 0; k < (Dn * Fn) / 256; ++k) {
    int idx = k * 256 + tid;
    int p = idx & 63;
    int l = idx >> 6;
    cl[p * 68 + l] = clast[l * Fn + p];
  }
  float xv[Fn];
  {
    const float4* xp =
        reinterpret_cast<const float4*>(x + (size_t)s * (Nn * Fn) + 7 * Fn);
#pragma unroll
    for (int k = 0; k < Fn / 4; ++k) {
      float4 t = xp[k];
      xv[4 * k] = t.x; xv[4 * k + 1] = t.y; xv[4 * k + 2] = t.z; xv[4 * k + 3] = t.w;
    }
  }
  __syncthreads();

  ull acc[8];
#pragma unroll
  for (int q = 0; q < 8; ++q) acc[q] = 0ull;
#pragma unroll 8
  for (int p = 0; p < Fn; ++p) {
    ull t2 = dup2(xv[p]);
    const ulonglong2* rp = reinterpret_cast<const ulonglong2*>(&cl[p * 68 + l0]);
#pragma unroll
    for (int q = 0; q < 4; ++q) {
      ulonglong2 cc = rp[q];
      acc[2 * q]     = ffma2(cc.x, t2, acc[2 * q]);
      acc[2 * q + 1] = ffma2(cc.y, t2, acc[2 * q + 1]);
    }
  }
#pragma unroll
  for (int q = 0; q < 8; ++q) {
    float a, b;
    unpack2(acc[q], a, b);
    g_v[(size_t)(l0 + 2 * q) * Bn + s] = a;
    g_v[(size_t)(l0 + 2 * q + 1) * Bn + s] = b;
  }
}

// ---------------------------------------------------------------------------
// mid step: partial[ks][l][s] = sum_{p in chunk of 4} sum_r W[l,p,r]*x*v
// grid (Bn/128, KS), 128 threads. Thread tile: 8 samples (4 pairs) x 8 l.
// Two staging phases of 2 p each (w2 buffer reused).
// ---------------------------------------------------------------------------
__global__ __launch_bounds__(128) void mid_step_kernel(const float* __restrict__ x,
                                                       int j, int tIdx) {
  extern __shared__ __align__(16) float sm[];
  float* v_t = sm + SM_VT;   // [r][s], stride VS
  float* w2  = sm + SM_W2;   // [2p][r][2l], stride 128 (per staging phase)
  float* x_t = sm + SM_XT;   // [p][s], stride VS (4 p)

  const int tid = threadIdx.x;
  const int si = tid & 15;   // sample octet
  const int li = tid >> 4;   // l octet
  const int s0 = blockIdx.x * 128;
  const int pbase = blockIdx.y * PC;

  // stage v_t: straight copy of g_v[r][s0..s0+127]
#pragma unroll
  for (int it = 0; it < 16; ++it) {
    int idx = it * 128 + tid;
    int c4 = idx & 31;
    int r = idx >> 5;
    float4 t = *reinterpret_cast<const float4*>(&g_v[(size_t)r * Bn + s0 + c4 * 4]);
    *reinterpret_cast<float4*>(&v_t[r * VS + c4 * 4]) = t;
  }
  // stage x_t[p][s] for 4 p
  {
    float4 t = *reinterpret_cast<const float4*>(
        x + (size_t)(s0 + tid) * (Nn * Fn) + (size_t)tIdx * Fn + pbase);
    x_t[0 * VS + tid] = t.x;
    x_t[1 * VS + tid] = t.y;
    x_t[2 * VS + tid] = t.z;
    x_t[3 * VS + tid] = t.w;
  }

  ull acc[4][8];
#pragma unroll
  for (int jj = 0; jj < 4; ++jj)
#pragma unroll
    for (int q = 0; q < 8; ++q) acc[jj][q] = 0ull;

#pragma unroll
  for (int phase = 0; phase < 2; ++phase) {
    if (phase) __syncthreads();  // previous compute done before w2 overwrite
    // stage w2 for p = pbase+2*phase, pbase+2*phase+1 (64KB straight copy)
    {
      const float4* srcw = reinterpret_cast<const float4*>(
          g_w2 + ((size_t)j * Fn + pbase + 2 * phase) * (Dn * 2 * Dn));
      float4* dstw = reinterpret_cast<float4*>(w2);
#pragma unroll
      for (int it = 0; it < (2 * Dn * 2 * Dn) / (4 * 128); ++it)
        dstw[it * 128 + tid] = srcw[it * 128 + tid];
    }
    __syncthreads();

    // x sample-pairs for this phase's two p
    ull xp0[4], xp1[4];
#pragma unroll
    for (int q = 0; q < 4; ++q) {
      xp0[q] = *reinterpret_cast<const ull*>(
          &x_t[(2 * phase + 0) * VS + si * 8 + 2 * q]);
      xp1[q] = *reinterpret_cast<const ull*>(
          &x_t[(2 * phase + 1) * VS + si * 8 + 2 * q]);
    }

#pragma unroll 4
    for (int r = 0; r < Dn; ++r) {
      const float* vrow = &v_t[r * VS + si * 8];
      ulonglong2 va = *reinterpret_cast<const ulonglong2*>(vrow);
      ulonglong2 vb = *reinterpret_cast<const ulonglong2*>(vrow + 4);

      // p = 2*phase
      {
        ull a0 = fmul2(va.x, xp0[0]);
        ull a1 = fmul2(va.y, xp0[1]);
        ull a2 = fmul2(vb.x, xp0[2]);
        ull a3 = fmul2(vb.y, xp0[3]);
        const ull* wrow =
            reinterpret_cast<const ull*>(&w2[(0 * Dn + r) * 128 + li * 16]);
#pragma unroll
        for (int q = 0; q < 8; ++q) {
          ull wq = wrow[q];
          acc[0][q] = ffma2(a0, wq, acc[0][q]);
          acc[1][q] = ffma2(a1, wq, acc[1][q]);
          acc[2][q] = ffma2(a2, wq, acc[2][q]);
          acc[3][q] = ffma2(a3, wq, acc[3][q]);
        }
      }
      // p = 2*phase+1
      {
        ull a0 = fmul2(va.x, xp1[0]);
        ull a1 = fmul2(va.y, xp1[1]);
        ull a2 = fmul2(vb.x, xp1[2]);
        ull a3 = fmul2(vb.y, xp1[3]);
        const ull* wrow =
            reinterpret_cast<const ull*>(&w2[(1 * Dn + r) * 128 + li * 16]);
#pragma unroll
        for (int q = 0; q < 8; ++q) {
          ull wq = wrow[q];
          acc[0][q] = ffma2(a0, wq, acc[0][q]);
          acc[1][q] = ffma2(a1, wq, acc[1][q]);
          acc[2][q] = ffma2(a2, wq, acc[2][q]);
          acc[3][q] = ffma2(a3, wq, acc[3][q]);
        }
      }
    }
  }

  // store partials: g_part[ks][l][s]
  float* op = g_part + (size_t)blockIdx.y * (Bn * Dn);
#pragma unroll
  for (int q = 0; q < 8; ++q) {
    int l = li * 8 + q;
#pragma unroll
    for (int jj = 0; jj < 4; ++jj) {
      float a, b;
      unpack2(acc[jj][q], a, b);
      *reinterpret_cast<float2*>(&op[(size_t)l * Bn + s0 + si * 8 + 2 * jj]) =
          make_float2(a, b);
    }
  }
}

// g_v[i] = sum_ks partial[ks][i], float4-vectorized
__global__ void reduce_v_kernel() {
  int i = blockIdx.x * blockDim.x + threadIdx.x;  // float4 index
  if (i < (Bn * Dn) / 4) {
    float4 sv = make_float4(0.f, 0.f, 0.f, 0.f);
#pragma unroll
    for (int k = 0; k < KS; ++k) {
      float4 t = reinterpret_cast<const float4*>(
          g_part + (size_t)k * Bn * Dn)[i];
      sv.x += t.x; sv.y += t.y; sv.z += t.z; sv.w += t.w;
    }
    reinterpret_cast<float4*>(g_v)[i] = sv;
  }
}

// ---------------------------------------------------------------------------
// final: partial_out[ks][s,c] = sum_{p in chunk} sum_r cfirst[c,p,r]*x[s,0,p]*v[r,s]
// ---------------------------------------------------------------------------
__global__ __launch_bounds__(128) void final_kernel(const float* __restrict__ x,
                                                    const float* __restrict__ cfirst) {
  __shared__ __align__(16) float fs[Dn * 12];  // [r][c]
  const int tid = threadIdx.x;
  const int s = blockIdx.x * 128 + tid;
  const int pbase = blockIdx.y * PCF;

  float vr[Dn];
#pragma unroll
  for (int r = 0; r < Dn; ++r) vr[r] = g_v[(size_t)r * Bn + s];

  float xr[PCF];
  {
    const float4* xp =
        reinterpret_cast<const float4*>(x + (size_t)s * (Nn * Fn) + pbase);
#pragma unroll
    for (int k = 0; k < PCF / 4; ++k) {
      float4 t = xp[k];
      xr[4 * k] = t.x; xr[4 * k + 1] = t.y; xr[4 * k + 2] = t.z; xr[4 * k + 3] = t.w;
    }
  }

  ull acc[5];
#pragma unroll
  for (int q = 0; q < 5; ++q) acc[q] = 0ull;

#pragma unroll 1
  for (int pp = 0; pp < PCF; ++pp) {
    __syncthreads();
    {
      const float* cp = cfirst + (size_t)(pbase + pp) * Dn;
#pragma unroll
      for (int k = 0; k < 5; ++k) {
        int idx = k * 128 + tid;
        int r = idx & 63;
        int c = idx >> 6;
        fs[r * 12 + c] = cp[(size_t)c * (Fn * Dn) + r];
      }
    }
    __syncthreads();
    const float xpv = xr[pp];
#pragma unroll 8
    for (int r = 0; r < Dn; ++r) {
      ull t2 = dup2(xpv * vr[r]);
      const float* base = &fs[r * 12];
      ulonglong2 a01 = *reinterpret_cast<const ulonglong2*>(base);
      ulonglong2 a23 = *reinterpret_cast<const ulonglong2*>(base + 4);
      ull a4 = *reinterpret_cast<const ull*>(base + 8);
      acc[0] = ffma2(a01.x, t2, acc[0]);
      acc[1] = ffma2(a01.y, t2, acc[1]);
      acc[2] = ffma2(a23.x, t2, acc[2]);
      acc[3] = ffma2(a23.y, t2, acc[3]);
      acc[4] = ffma2(a4, t2, acc[4]);
    }
  }

  float o[10];
#pragma unroll
  for (int q = 0; q < 5; ++q) unpack2(acc[q], o[2 * q], o[2 * q + 1]);
  float* op = g_part + ((size_t)blockIdx.y * Bn + s) * 12;
  reinterpret_cast<float4*>(op)[0] = make_float4(o[0], o[1], o[2], o[3]);
  reinterpret_cast<float4*>(op)[1] = make_float4(o[4], o[5], o[6], o[7]);
  reinterpret_cast<float2*>(op + 8)[0] = make_float2(o[8], o[9]);
}

__global__ void reduce_out_kernel(float* __restrict__ out) {
  int i = blockIdx.x * blockDim.x + threadIdx.x;
  if (i < Bn * Cn) {
    int s = i / Cn;
    int c = i - s * Cn;
    float acc = 0.f;
#pragma unroll
    for (int k = 0; k < KSF; ++k) acc += g_part[((size_t)k * Bn + s) * 12 + c];
    out[i] = acc;
  }
}

}  // namespace

extern "C" void kernel_launch(void* const* d_in, const int* in_sizes, int n_in,
                              void* d_out, int out_size) {
  const float* x = (const float*)d_in[0];       // (4096, 8, 64)
  const float* cfirst = (const float*)d_in[1];  // (10, 64, 64)
  const float* cmid = (const float*)d_in[2];    // (6, 64, 64, 64)
  const float* clast = (const float*)d_in[3];   // (64, 64)
  float* out = (float*)d_out;                   // (4096, 10)

  static bool attr_done = false;
  if (!attr_done) {
    cudaFuncSetAttribute(mid_step_kernel,
                         cudaFuncAttributeMaxDynamicSharedMemorySize,
                         SM_MID_BYTES);
    attr_done = true;
  }

  preconv_w_kernel<<<NMID * Fn, 256>>>(cmid);
  init_v_kernel<<<Bn / 64, 256>>>(x, clast);

  for (int j = NMID - 1; j >= 0; --j) {
    mid_step_kernel<<<dim3(Bn / 128, KS), 128, SM_MID_BYTES>>>(x, j, j + 1);
    reduce_v_kernel<<<(Bn * Dn / 4 + 255) / 256, 256>>>();
  }

  final_kernel<<<dim3(Bn / 128, KSF), 128>>>(x, cfirst);
  reduce_out_kernel<<<(Bn * Cn + 255) / 256, 256>>>(out);
}